// round 2
// baseline (speedup 1.0000x reference)
#include <cuda_runtime.h>
#include <cuda_bf16.h>

#define BB 8
#define HH 512
#define WW 512
#define NN 128
#define TS 32

// scratch (device globals: no allocation allowed)
__device__ float g_cy[BB * NN];
__device__ float g_cx[BB * NN];
__device__ float g_inv[BB * NN];
__device__ double g_scale_sum;
__device__ double g_hm_sum;

// ---------------------------------------------------------------------------
// Kernel A: per-(b,n) sigma prep + accumulator zeroing
// ---------------------------------------------------------------------------
__global__ void prep_kernel(const float* __restrict__ sm,
                            const float* __restrict__ gr,
                            const int* __restrict__ centers) {
    int t = blockIdx.x * blockDim.x + threadIdx.x;
    if (t == 0) {
        g_scale_sum = 0.0;
        g_hm_sum = 0.0;
    }
    if (t >= BB * NN) return;
    int b = t / NN;
    int c0 = centers[2 * t];
    int c1 = centers[2 * t + 1];
    c0 = min(max(c0, 0), HH - 1);
    c1 = min(max(c1, 0), WW - 1);
    float s = sm[(long)b * HH * WW + c0 * WW + c1];
    float g = gr[b];
    // sizes = PR_MIN/gr + relu(sm)*REF_GROUND_RES/gr  (PR_MIN=REF_GROUND_RES=0.2)
    float sigma = 0.2f / g + fmaxf(s, 0.0f) * 0.2f / g;
    float inv = -1.0f / (2.0f * sigma * sigma);
    g_cy[t] = (float)c0;
    g_cx[t] = (float)c1;
    g_inv[t] = inv;
}

// ---------------------------------------------------------------------------
// Kernel B: per 32x32 tile: prune centers, gt = exp(max arg), fused reductions
// ---------------------------------------------------------------------------
__global__ void __launch_bounds__(256) gt_kernel(const float* __restrict__ hm,
                                                 const float* __restrict__ sm,
                                                 const float* __restrict__ mask,
                                                 float* __restrict__ out) {
    __shared__ float s_cy[NN], s_cx[NN], s_inv[NN];
    __shared__ int s_cnt;
    __shared__ float sh_hm[8], sh_sc[8];

    const int b = blockIdx.z;
    const int y0 = blockIdx.y * TS;
    const int x0 = blockIdx.x * TS;
    const int t = threadIdx.x;

    if (t == 0) s_cnt = 0;
    __syncthreads();

    // --- prune: keep centers whose best achievable arg in this tile >= -104
    // (expf(arg) == exactly 0.0f for arg < -103.98, so dropped centers are
    //  exactly-zero contributors in the reference as well)
    if (t < NN) {
        int idx = b * NN + t;
        float cy = g_cy[idx], cx = g_cx[idx], inv = g_inv[idx];
        float dy = fmaxf(fmaxf((float)y0 - cy, cy - (float)(y0 + TS - 1)), 0.0f);
        float dx = fmaxf(fmaxf((float)x0 - cx, cx - (float)(x0 + TS - 1)), 0.0f);
        float mind2 = fmaf(dy, dy, dx * dx);
        if (mind2 * inv >= -104.0f) {
            int p = atomicAdd(&s_cnt, 1);
            s_cy[p] = cy;
            s_cx[p] = cx;
            s_inv[p] = inv;
        }
    }
    __syncthreads();
    const int cnt = s_cnt;

    // --- each thread: 4 consecutive pixels of one row
    const int ry = t >> 3;
    const int x = x0 + ((t & 7) << 2);
    const int y = y0 + ry;
    const long base = (long)b * HH * WW + (long)y * WW + x;

    const float4 h4 = *(const float4*)(hm + base);
    const float4 s4 = *(const float4*)(sm + base);
    const float4 m4 = *(const float4*)(mask + base);

    const float yf = (float)y;
    float best0 = -3.0e38f, best1 = -3.0e38f, best2 = -3.0e38f, best3 = -3.0e38f;
    const float xf0 = (float)x, xf1 = (float)(x + 1), xf2 = (float)(x + 2), xf3 = (float)(x + 3);

    for (int i = 0; i < cnt; i++) {
        float cy = s_cy[i], cx = s_cx[i], inv = s_inv[i];
        float dy = yf - cy;
        float dy2 = dy * dy;
        float dx0 = xf0 - cx, dx1 = xf1 - cx, dx2 = xf2 - cx, dx3 = xf3 - cx;
        best0 = fmaxf(best0, fmaf(dx0, dx0, dy2) * inv);
        best1 = fmaxf(best1, fmaf(dx1, dx1, dy2) * inv);
        best2 = fmaxf(best2, fmaf(dx2, dx2, dy2) * inv);
        best3 = fmaxf(best3, fmaf(dx3, dx3, dy2) * inv);
    }

    float g0 = (cnt > 0) ? __expf(best0) : 0.0f;
    float g1 = (cnt > 0) ? __expf(best1) : 0.0f;
    float g2 = (cnt > 0) ? __expf(best2) : 0.0f;
    float g3 = (cnt > 0) ? __expf(best3) : 0.0f;

    // gt output lives at out+2 -> only 8B aligned; use float2 stores
    float* gout = out + 2 + base;
    *(float2*)(gout) = make_float2(g0, g1);
    *(float2*)(gout + 2) = make_float2(g2, g3);

    // fused reductions
    float d0 = h4.x - g0, d1 = h4.y - g1, d2 = h4.z - g2, d3 = h4.w - g3;
    float hm_acc = d0 * d0 * m4.x + d1 * d1 * m4.y + d2 * d2 * m4.z + d3 * d3 * m4.w;
    float sc_acc = s4.x * s4.x + s4.y * s4.y + s4.z * s4.z + s4.w * s4.w;

    #pragma unroll
    for (int o = 16; o; o >>= 1) {
        hm_acc += __shfl_down_sync(0xFFFFFFFFu, hm_acc, o);
        sc_acc += __shfl_down_sync(0xFFFFFFFFu, sc_acc, o);
    }
    const int lane = t & 31, wid = t >> 5;
    if (lane == 0) {
        sh_hm[wid] = hm_acc;
        sh_sc[wid] = sc_acc;
    }
    __syncthreads();
    if (t == 0) {
        double ah = 0.0, as = 0.0;
        #pragma unroll
        for (int k = 0; k < 8; k++) {
            ah += (double)sh_hm[k];
            as += (double)sh_sc[k];
        }
        atomicAdd(&g_hm_sum, ah);
        atomicAdd(&g_scale_sum, as);
    }
}

// ---------------------------------------------------------------------------
// Kernel C: finalize the two scalar means
// ---------------------------------------------------------------------------
__global__ void final_kernel(float* __restrict__ out) {
    const double invn = 1.0 / ((double)BB * HH * WW);
    out[0] = (float)(g_scale_sum * invn);
    out[1] = (float)(g_hm_sum * invn);
}

extern "C" void kernel_launch(void* const* d_in, const int* in_sizes, int n_in,
                              void* d_out, int out_size) {
    const float* hm = (const float*)d_in[0];       // pred_hm [8,1,512,512]
    const float* sm = (const float*)d_in[1];       // pred_sm [8,1,512,512]
    const float* gr = (const float*)d_in[2];       // ground_resolution [8]
    const float* mask = (const float*)d_in[3];     // mask [8,1,512,512]
    const int* centers = (const int*)d_in[4];      // centers [8,128,2]
    float* out = (float*)d_out;                    // [scale_loss, hm_loss, gts...]

    prep_kernel<<<1, BB * NN>>>(sm, gr, centers);
    dim3 grid(WW / TS, HH / TS, BB);
    gt_kernel<<<grid, 256>>>(hm, sm, mask, out);
    final_kernel<<<1, 1>>>(out);
}

// round 3
// speedup vs baseline: 1.1363x; 1.1363x over previous
#include <cuda_runtime.h>
#include <cuda_bf16.h>

#define BB 8
#define HH 512
#define WW 512
#define NN 128
#define TS 32
#define NBLK (BB * (HH / TS) * (WW / TS))   // 2048 tile blocks

// scratch (device globals: allocation is forbidden)
__device__ float g_part_hm[NBLK];
__device__ float g_part_sc[NBLK];

// ---------------------------------------------------------------------------
// Kernel 1: per 32x32 tile — inline sigma prep + exact prune,
//           gt = exp(max arg), fused partial reductions (no atomics)
// ---------------------------------------------------------------------------
__global__ void __launch_bounds__(256) gt_kernel(const float* __restrict__ hm,
                                                 const float* __restrict__ sm,
                                                 const float* __restrict__ mask,
                                                 const float* __restrict__ gr,
                                                 const int* __restrict__ centers,
                                                 float* __restrict__ out) {
    __shared__ float s_cy[NN], s_cx[NN], s_inv[NN];
    __shared__ int s_cnt;
    __shared__ float sh_hm[8], sh_sc[8];

    const int b = blockIdx.z;
    const int y0 = blockIdx.y * TS;
    const int x0 = blockIdx.x * TS;
    const int t = threadIdx.x;

    if (t == 0) s_cnt = 0;
    __syncthreads();

    // --- inline prep + prune. expf(arg) == exactly 0.0f for arg < -103.98,
    // so centers whose best achievable arg in this tile is < -104 contribute
    // exactly 0 in the reference too (bit-safe pruning).
    if (t < NN) {
        const int2 c = ((const int2*)centers)[b * NN + t];
        const int c0 = min(max(c.x, 0), HH - 1);
        const int c1 = min(max(c.y, 0), WW - 1);
        const float s = __ldg(sm + (long)b * HH * WW + c0 * WW + c1);
        const float g = gr[b];
        // sigma = PR_MIN/gr + relu(sm)*REF_GROUND_RES/gr   (both = 0.2)
        const float sigma = 0.2f / g + fmaxf(s, 0.0f) * 0.2f / g;
        const float inv = -1.0f / (2.0f * sigma * sigma);
        const float cy = (float)c0, cx = (float)c1;
        float dy = fmaxf(fmaxf((float)y0 - cy, cy - (float)(y0 + TS - 1)), 0.0f);
        float dx = fmaxf(fmaxf((float)x0 - cx, cx - (float)(x0 + TS - 1)), 0.0f);
        float mind2 = fmaf(dy, dy, dx * dx);
        if (mind2 * inv >= -104.0f) {
            int p = atomicAdd(&s_cnt, 1);
            s_cy[p] = cy;
            s_cx[p] = cx;
            s_inv[p] = inv;
        }
    }
    __syncthreads();
    const int cnt = s_cnt;

    // --- each thread: 4 consecutive pixels of one tile row
    const int x = x0 + ((t & 7) << 2);
    const int y = y0 + (t >> 3);
    const long base = (long)b * HH * WW + (long)y * WW + x;

    const float4 h4 = *(const float4*)(hm + base);
    const float4 s4 = *(const float4*)(sm + base);
    const float4 m4 = *(const float4*)(mask + base);

    const float yf = (float)y;
    float best0 = -3.0e38f, best1 = -3.0e38f, best2 = -3.0e38f, best3 = -3.0e38f;
    const float xf0 = (float)x, xf1 = xf0 + 1.0f, xf2 = xf0 + 2.0f, xf3 = xf0 + 3.0f;

    for (int i = 0; i < cnt; i++) {
        float cy = s_cy[i], cx = s_cx[i], inv = s_inv[i];
        float dy = yf - cy;
        float dy2 = dy * dy;
        float dx0 = xf0 - cx, dx1 = xf1 - cx, dx2 = xf2 - cx, dx3 = xf3 - cx;
        best0 = fmaxf(best0, fmaf(dx0, dx0, dy2) * inv);
        best1 = fmaxf(best1, fmaf(dx1, dx1, dy2) * inv);
        best2 = fmaxf(best2, fmaf(dx2, dx2, dy2) * inv);
        best3 = fmaxf(best3, fmaf(dx3, dx3, dy2) * inv);
    }

    const float g0 = (cnt > 0) ? __expf(best0) : 0.0f;
    const float g1 = (cnt > 0) ? __expf(best1) : 0.0f;
    const float g2 = (cnt > 0) ? __expf(best2) : 0.0f;
    const float g3 = (cnt > 0) ? __expf(best3) : 0.0f;

    // gt output lives at out+2 -> only 8B aligned; float2 stores
    float* gout = out + 2 + base;
    *(float2*)(gout) = make_float2(g0, g1);
    *(float2*)(gout + 2) = make_float2(g2, g3);

    // fused partial reductions
    float d0 = h4.x - g0, d1 = h4.y - g1, d2 = h4.z - g2, d3 = h4.w - g3;
    float hm_acc = d0 * d0 * m4.x + d1 * d1 * m4.y + d2 * d2 * m4.z + d3 * d3 * m4.w;
    float sc_acc = s4.x * s4.x + s4.y * s4.y + s4.z * s4.z + s4.w * s4.w;

    #pragma unroll
    for (int o = 16; o; o >>= 1) {
        hm_acc += __shfl_down_sync(0xFFFFFFFFu, hm_acc, o);
        sc_acc += __shfl_down_sync(0xFFFFFFFFu, sc_acc, o);
    }
    const int lane = t & 31, wid = t >> 5;
    if (lane == 0) {
        sh_hm[wid] = hm_acc;
        sh_sc[wid] = sc_acc;
    }
    __syncthreads();
    if (t == 0) {
        float ah = 0.0f, as = 0.0f;
        #pragma unroll
        for (int k = 0; k < 8; k++) {
            ah += sh_hm[k];
            as += sh_sc[k];
        }
        const int bid = (blockIdx.z * gridDim.y + blockIdx.y) * gridDim.x + blockIdx.x;
        g_part_hm[bid] = ah;   // plain stores: each block owns its slot
        g_part_sc[bid] = as;
    }
}

// ---------------------------------------------------------------------------
// Kernel 2: reduce 2048 partials -> two scalar means
// ---------------------------------------------------------------------------
__global__ void __launch_bounds__(256) final_kernel(float* __restrict__ out) {
    __shared__ double sh_h[8], sh_s[8];
    const int t = threadIdx.x;
    double ah = 0.0, as = 0.0;
    #pragma unroll
    for (int k = 0; k < NBLK / 256; k++) {
        ah += (double)g_part_hm[t + k * 256];
        as += (double)g_part_sc[t + k * 256];
    }
    #pragma unroll
    for (int o = 16; o; o >>= 1) {
        ah += __shfl_down_sync(0xFFFFFFFFu, ah, o);
        as += __shfl_down_sync(0xFFFFFFFFu, as, o);
    }
    const int lane = t & 31, wid = t >> 5;
    if (lane == 0) { sh_h[wid] = ah; sh_s[wid] = as; }
    __syncthreads();
    if (t == 0) {
        double th = 0.0, ts = 0.0;
        #pragma unroll
        for (int k = 0; k < 8; k++) { th += sh_h[k]; ts += sh_s[k]; }
        const double invn = 1.0 / ((double)BB * HH * WW);
        out[0] = (float)(ts * invn);
        out[1] = (float)(th * invn);
    }
}

extern "C" void kernel_launch(void* const* d_in, const int* in_sizes, int n_in,
                              void* d_out, int out_size) {
    const float* hm = (const float*)d_in[0];       // pred_hm [8,1,512,512]
    const float* sm = (const float*)d_in[1];       // pred_sm [8,1,512,512]
    const float* gr = (const float*)d_in[2];       // ground_resolution [8]
    const float* mask = (const float*)d_in[3];     // mask [8,1,512,512]
    const int* centers = (const int*)d_in[4];      // centers [8,128,2]
    float* out = (float*)d_out;                    // [scale_loss, hm_loss, gts...]

    dim3 grid(WW / TS, HH / TS, BB);
    gt_kernel<<<grid, 256>>>(hm, sm, mask, gr, centers, out);
    final_kernel<<<1, 256>>>(out);
}